// round 2
// baseline (speedup 1.0000x reference)
#include <cuda_runtime.h>
#include <math.h>

// Problem constants
constexpr int B  = 4;
constexpr int T  = 2048;
constexpr int C  = 1024;
constexpr int H  = 16;
constexpr int D  = 64;      // C / H
constexpr int FF = 2048;    // 2 * C
constexpr int M  = B * T;   // 8192 rows

// ---------------------------------------------------------------------------
// Scratch (device globals; no allocation allowed in kernel_launch)
// ---------------------------------------------------------------------------
__device__ float g_h  [(size_t)M * C];      // LN output (reused for LN1 and LN2)
__device__ float g_qkv[(size_t)M * 3 * C];  // QKV projection
__device__ float g_att[(size_t)M * C];      // attention output y
__device__ float g_x2 [(size_t)M * C];      // x + y@Wproj + bproj
__device__ float g_ff [(size_t)M * FF];     // gelu(h2@Wff1 + bff1)

// ---------------------------------------------------------------------------
// LayerNorm: one block per row of 1024, 256 threads, 4 elems/thread
// ---------------------------------------------------------------------------
__global__ void ln_kernel(const float* __restrict__ x,
                          const float* __restrict__ gamma,
                          const float* __restrict__ beta,
                          float* __restrict__ out) {
    int row = blockIdx.x;
    int tid = threadIdx.x;
    const float4* xr = (const float4*)(x + (size_t)row * C);
    float4 v = xr[tid];

    float s  = v.x + v.y + v.z + v.w;
    float sq = v.x * v.x + v.y * v.y + v.z * v.z + v.w * v.w;
    #pragma unroll
    for (int o = 16; o > 0; o >>= 1) {
        s  += __shfl_xor_sync(0xffffffffu, s,  o);
        sq += __shfl_xor_sync(0xffffffffu, sq, o);
    }
    __shared__ float ss[8], ssq[8];
    __shared__ float mu_s, rs_s;
    int w = tid >> 5;
    if ((tid & 31) == 0) { ss[w] = s; ssq[w] = sq; }
    __syncthreads();
    if (tid == 0) {
        float S = 0.f, SQ = 0.f;
        #pragma unroll
        for (int i = 0; i < 8; i++) { S += ss[i]; SQ += ssq[i]; }
        float mu  = S * (1.0f / (float)C);
        float var = SQ * (1.0f / (float)C) - mu * mu;
        mu_s = mu;
        rs_s = rsqrtf(var + 1e-5f);
    }
    __syncthreads();
    float mu = mu_s, rs = rs_s;
    float4 gv = ((const float4*)gamma)[tid];
    float4 bv = ((const float4*)beta)[tid];
    float4 o4;
    o4.x = (v.x - mu) * rs * gv.x + bv.x;
    o4.y = (v.y - mu) * rs * gv.y + bv.y;
    o4.z = (v.z - mu) * rs * gv.z + bv.z;
    o4.w = (v.w - mu) * rs * gv.w + bv.w;
    ((float4*)(out + (size_t)row * C))[tid] = o4;
}

// ---------------------------------------------------------------------------
// Tiled fp32 GEMM: Cout[Mn,Nn] = A[Mn,Kn] @ Bm[Kn,Nn] (+bias/gelu/residual)
// BM=BN=128, BK=16, 256 threads, 8x8 register tile per thread.
// EPI: 0 = plain, 1 = +bias +residual, 2 = +bias then exact GELU
// ---------------------------------------------------------------------------
template <int EPI>
__global__ __launch_bounds__(256) void sgemm_kernel(
    const float* __restrict__ A, const float* __restrict__ Bm,
    const float* __restrict__ bias, const float* __restrict__ res,
    float* __restrict__ Cout, int Mn, int Nn, int Kn) {
    __shared__ float As[16][128];   // transposed A tile: As[k][m]
    __shared__ float Bs[16][128];

    int tid  = threadIdx.x;
    int row0 = blockIdx.y * 128;
    int col0 = blockIdx.x * 128;
    int ty = tid >> 4, tx = tid & 15;

    float acc[8][8];
    #pragma unroll
    for (int i = 0; i < 8; i++)
        #pragma unroll
        for (int j = 0; j < 8; j++) acc[i][j] = 0.f;

    const float* Aptr = A  + (size_t)row0 * Kn;
    const float* Bptr = Bm + col0;

    for (int k0 = 0; k0 < Kn; k0 += 16) {
        #pragma unroll
        for (int t = 0; t < 2; t++) {
            int p = tid + t * 256;
            int ar = p >> 2, ac = p & 3;
            float4 av = *(const float4*)(Aptr + (size_t)ar * Kn + k0 + ac * 4);
            As[ac * 4 + 0][ar] = av.x;
            As[ac * 4 + 1][ar] = av.y;
            As[ac * 4 + 2][ar] = av.z;
            As[ac * 4 + 3][ar] = av.w;
            int br = p >> 5, bc = p & 31;
            *(float4*)&Bs[br][bc * 4] =
                *(const float4*)(Bptr + (size_t)(k0 + br) * Nn + bc * 4);
        }
        __syncthreads();
        #pragma unroll
        for (int kk = 0; kk < 16; kk++) {
            float ra[8], rb[8];
            *(float4*)(ra)     = *(const float4*)&As[kk][ty * 8];
            *(float4*)(ra + 4) = *(const float4*)&As[kk][ty * 8 + 4];
            *(float4*)(rb)     = *(const float4*)&Bs[kk][tx * 8];
            *(float4*)(rb + 4) = *(const float4*)&Bs[kk][tx * 8 + 4];
            #pragma unroll
            for (int i = 0; i < 8; i++)
                #pragma unroll
                for (int j = 0; j < 8; j++) acc[i][j] += ra[i] * rb[j];
        }
        __syncthreads();
    }

    #pragma unroll
    for (int i = 0; i < 8; i++) {
        int r = row0 + ty * 8 + i;
        #pragma unroll
        for (int j = 0; j < 8; j++) {
            int c = col0 + tx * 8 + j;
            float v = acc[i][j];
            if (EPI == 1) {
                v += bias[c];
                v += res[(size_t)r * Nn + c];
            } else if (EPI == 2) {
                v += bias[c];
                v = 0.5f * v * (1.0f + erff(v * 0.70710678118654752f));
            }
            Cout[(size_t)r * Nn + c] = v;
        }
    }
}

// ---------------------------------------------------------------------------
// Flash attention with permutation mask: key k is legal for query q iff
// perm[k] <= q. Scores scaled by 1/sqrt(D)=0.125.
// Block: 64 query rows x full D=64, loops over 32 key tiles of 64.
// 256 threads: thread (r = tid/4, cg = tid%3..) -> owns (row r, 16 cols).
// Smem: Qs[64][65], KPs[64][65] (K tile, then aliased as P tile), Vs[64][65].
// ---------------------------------------------------------------------------
constexpr int ATTN_SMEM = (3 * 64 * 65) * 4 + 64 * 4;  // 50176 B

__global__ __launch_bounds__(256) void attn_kernel(
    const float* __restrict__ qkv, const int* __restrict__ perm,
    float* __restrict__ out) {
    extern __shared__ float sm[];
    float* Qs  = sm;                 // [64][65]
    float* KPs = Qs  + 64 * 65;      // [64][65]  K tile, reused for P
    float* Vs  = KPs + 64 * 65;      // [64][65]
    int*   permS = (int*)(Vs + 64 * 65);  // [64]

    int tid = threadIdx.x;
    int qt = blockIdx.x, h = blockIdx.y, b = blockIdx.z;
    int q0 = qt * 64;
    int r  = tid >> 2;   // query row within tile (0..63)
    int cg = tid & 3;    // column group (0..3), 16 cols each

    // Load Q tile (64x64): global float4 loads, scalar smem stores (stride 65)
    #pragma unroll
    for (int t = 0; t < 4; t++) {
        int p  = tid + t * 256;
        int qr = p >> 4, c4 = p & 15;
        float4 v = *(const float4*)(qkv + ((size_t)(b * T + q0 + qr)) * (3 * C)
                                        + h * D + c4 * 4);
        Qs[qr * 65 + c4 * 4 + 0] = v.x;
        Qs[qr * 65 + c4 * 4 + 1] = v.y;
        Qs[qr * 65 + c4 * 4 + 2] = v.z;
        Qs[qr * 65 + c4 * 4 + 3] = v.w;
    }

    float m = -1e30f, l = 0.f;
    float o[16];
    #pragma unroll
    for (int j = 0; j < 16; j++) o[j] = 0.f;

    int q = q0 + r;

    for (int k0 = 0; k0 < T; k0 += 64) {
        __syncthreads();  // prior O-update done reading KPs/Vs (and Q visible, iter 0)
        // Load K and V tiles
        #pragma unroll
        for (int t = 0; t < 4; t++) {
            int p  = tid + t * 256;
            int kr = p >> 4, c4 = p & 15;
            size_t base = ((size_t)(b * T + k0 + kr)) * (3 * C) + h * D + c4 * 4;
            float4 kv = *(const float4*)(qkv + base + C);
            KPs[kr * 65 + c4 * 4 + 0] = kv.x;
            KPs[kr * 65 + c4 * 4 + 1] = kv.y;
            KPs[kr * 65 + c4 * 4 + 2] = kv.z;
            KPs[kr * 65 + c4 * 4 + 3] = kv.w;
            float4 vv = *(const float4*)(qkv + base + 2 * C);
            Vs[kr * 65 + c4 * 4 + 0] = vv.x;
            Vs[kr * 65 + c4 * 4 + 1] = vv.y;
            Vs[kr * 65 + c4 * 4 + 2] = vv.z;
            Vs[kr * 65 + c4 * 4 + 3] = vv.w;
        }
        if (tid < 64) permS[tid] = perm[k0 + tid];
        __syncthreads();

        // S = Q @ K^T for this thread's 16 columns, with scale + mask
        float s[16];
        #pragma unroll
        for (int cc = 0; cc < 16; cc++) {
            const float* kp = &KPs[(cg * 16 + cc) * 65];
            const float* qp = &Qs[r * 65];
            float a0 = 0.f, a1 = 0.f, a2 = 0.f, a3 = 0.f;
            #pragma unroll
            for (int d = 0; d < 64; d += 4) {
                a0 += qp[d + 0] * kp[d + 0];
                a1 += qp[d + 1] * kp[d + 1];
                a2 += qp[d + 2] * kp[d + 2];
                a3 += qp[d + 3] * kp[d + 3];
            }
            float sc = (a0 + a1) + (a2 + a3);
            s[cc] = (permS[cg * 16 + cc] > q) ? -1e30f : sc * 0.125f;
        }

        // Online softmax (row shared by 4 consecutive lanes -> shfl_xor 1,2)
        float tmax = s[0];
        #pragma unroll
        for (int cc = 1; cc < 16; cc++) tmax = fmaxf(tmax, s[cc]);
        tmax = fmaxf(tmax, __shfl_xor_sync(0xffffffffu, tmax, 1));
        tmax = fmaxf(tmax, __shfl_xor_sync(0xffffffffu, tmax, 2));

        float mn = fmaxf(m, tmax);
        float alpha = __expf(m - mn);
        float ls = 0.f;
        #pragma unroll
        for (int cc = 0; cc < 16; cc++) {
            s[cc] = __expf(s[cc] - mn);
            ls += s[cc];
        }
        ls += __shfl_xor_sync(0xffffffffu, ls, 1);
        ls += __shfl_xor_sync(0xffffffffu, ls, 2);
        l = l * alpha + ls;
        m = mn;
        #pragma unroll
        for (int j = 0; j < 16; j++) o[j] *= alpha;

        __syncthreads();  // everyone done reading KPs as K
        #pragma unroll
        for (int cc = 0; cc < 16; cc++) KPs[r * 65 + cg * 16 + cc] = s[cc];
        __syncthreads();  // P visible

        // O += P @ V
        #pragma unroll 8
        for (int k = 0; k < 64; k++) {
            float p = KPs[r * 65 + k];
            const float* vp = &Vs[k * 65 + cg * 16];
            #pragma unroll
            for (int j = 0; j < 16; j++) o[j] += p * vp[j];
        }
    }

    float inv = 1.0f / l;
    float* op = out + ((size_t)(b * T + q)) * C + h * D + cg * 16;
    #pragma unroll
    for (int j = 0; j < 16; j++) op[j] = o[j] * inv;
}

// ---------------------------------------------------------------------------
// Launch
// ---------------------------------------------------------------------------
extern "C" void kernel_launch(void* const* d_in, const int* in_sizes, int n_in,
                              void* d_out, int out_size) {
    (void)in_sizes; (void)n_in; (void)out_size;
    const float* x     = (const float*)d_in[0];
    const int*   perm  = (const int*)d_in[1];
    const float* Wqkv  = (const float*)d_in[2];
    const float* Wproj = (const float*)d_in[3];
    const float* bproj = (const float*)d_in[4];
    const float* ln1_g = (const float*)d_in[5];
    const float* ln1_b = (const float*)d_in[6];
    const float* ln2_g = (const float*)d_in[7];
    const float* ln2_b = (const float*)d_in[8];
    const float* Wff1  = (const float*)d_in[9];
    const float* bff1  = (const float*)d_in[10];
    const float* Wff2  = (const float*)d_in[11];
    const float* bff2  = (const float*)d_in[12];
    float* out = (float*)d_out;

    void *ph, *pqkv, *patt, *px2, *pff;
    cudaGetSymbolAddress(&ph,   g_h);
    cudaGetSymbolAddress(&pqkv, g_qkv);
    cudaGetSymbolAddress(&patt, g_att);
    cudaGetSymbolAddress(&px2,  g_x2);
    cudaGetSymbolAddress(&pff,  g_ff);
    float* h   = (float*)ph;
    float* qkv = (float*)pqkv;
    float* att = (float*)patt;
    float* x2  = (float*)px2;
    float* ff  = (float*)pff;

    cudaFuncSetAttribute(attn_kernel,
                         cudaFuncAttributeMaxDynamicSharedMemorySize, ATTN_SMEM);

    // 1. h = LN1(x)
    ln_kernel<<<M, 256>>>(x, ln1_g, ln1_b, h);
    // 2. qkv = h @ Wqkv
    sgemm_kernel<0><<<dim3(3 * C / 128, M / 128), 256>>>(
        h, Wqkv, nullptr, nullptr, qkv, M, 3 * C, C);
    // 3. attention -> att
    attn_kernel<<<dim3(T / 64, H, B), 256, ATTN_SMEM>>>(qkv, perm, att);
    // 4. x2 = x + att @ Wproj + bproj
    sgemm_kernel<1><<<dim3(C / 128, M / 128), 256>>>(
        att, Wproj, bproj, x, x2, M, C, C);
    // 5. h = LN2(x2)
    ln_kernel<<<M, 256>>>(x2, ln2_g, ln2_b, h);
    // 6. ff = gelu(h @ Wff1 + bff1)
    sgemm_kernel<2><<<dim3(FF / 128, M / 128), 256>>>(
        h, Wff1, bff1, nullptr, ff, M, FF, C);
    // 7. out = x2 + ff @ Wff2 + bff2
    sgemm_kernel<1><<<dim3(C / 128, M / 128), 256>>>(
        ff, Wff2, bff2, x2, out, M, C, FF);
}

// round 3
// speedup vs baseline: 14.2247x; 14.2247x over previous
#include <cuda_runtime.h>
#include <math.h>
#include <stdint.h>

// Problem constants
constexpr int Bb = 4;
constexpr int Tt = 2048;
constexpr int Cc = 1024;
constexpr int Hh = 16;
constexpr int Dd = 64;
constexpr int FFf = 2048;
constexpr int Mm = Bb * Tt;   // 8192

// ---------------------------------------------------------------------------
// Scratch (device globals; no allocation allowed)
// ---------------------------------------------------------------------------
__device__ float g_h  [(size_t)Mm * Cc];
__device__ float g_qkv[(size_t)Mm * 3 * Cc];
__device__ float g_att[(size_t)Mm * Cc];
__device__ float g_x2 [(size_t)Mm * Cc];
__device__ float g_ff [(size_t)Mm * FFf];

// ---------------------------------------------------------------------------
// tf32 mma.sync wrapper (m16n8k8, row.col, fp32 accumulate)
// Raw fp32 bits are fed as tf32 operands (HW truncates low mantissa bits).
// ---------------------------------------------------------------------------
__device__ __forceinline__ void mma_tf32(float* c, const uint32_t* a, const uint32_t* b) {
    asm volatile(
        "mma.sync.aligned.m16n8k8.row.col.f32.tf32.tf32.f32 "
        "{%0,%1,%2,%3}, {%4,%5,%6,%7}, {%8,%9}, {%0,%1,%2,%3};\n"
        : "+f"(c[0]), "+f"(c[1]), "+f"(c[2]), "+f"(c[3])
        : "r"(a[0]), "r"(a[1]), "r"(a[2]), "r"(a[3]), "r"(b[0]), "r"(b[1]));
}

__device__ __forceinline__ void cp16(uint32_t saddr, const void* g) {
    asm volatile("cp.async.cg.shared.global [%0], [%1], 16;\n" :: "r"(saddr), "l"(g));
}

// ---------------------------------------------------------------------------
// LayerNorm: one block per row of 1024, 256 threads
// ---------------------------------------------------------------------------
__global__ void ln_kernel(const float* __restrict__ x,
                          const float* __restrict__ gamma,
                          const float* __restrict__ beta,
                          float* __restrict__ out) {
    int row = blockIdx.x;
    int tid = threadIdx.x;
    const float4* xr = (const float4*)(x + (size_t)row * Cc);
    float4 v = xr[tid];

    float s  = v.x + v.y + v.z + v.w;
    float sq = v.x * v.x + v.y * v.y + v.z * v.z + v.w * v.w;
    #pragma unroll
    for (int o = 16; o > 0; o >>= 1) {
        s  += __shfl_xor_sync(0xffffffffu, s,  o);
        sq += __shfl_xor_sync(0xffffffffu, sq, o);
    }
    __shared__ float ss[8], ssq[8];
    __shared__ float mu_s, rs_s;
    int w = tid >> 5;
    if ((tid & 31) == 0) { ss[w] = s; ssq[w] = sq; }
    __syncthreads();
    if (tid == 0) {
        float S = 0.f, SQ = 0.f;
        #pragma unroll
        for (int i = 0; i < 8; i++) { S += ss[i]; SQ += ssq[i]; }
        float mu  = S * (1.0f / (float)Cc);
        float var = SQ * (1.0f / (float)Cc) - mu * mu;
        mu_s = mu;
        rs_s = rsqrtf(var + 1e-5f);
    }
    __syncthreads();
    float mu = mu_s, rs = rs_s;
    float4 gv = ((const float4*)gamma)[tid];
    float4 bv = ((const float4*)beta)[tid];
    float4 o4;
    o4.x = (v.x - mu) * rs * gv.x + bv.x;
    o4.y = (v.y - mu) * rs * gv.y + bv.y;
    o4.z = (v.z - mu) * rs * gv.z + bv.z;
    o4.w = (v.w - mu) * rs * gv.w + bv.w;
    ((float4*)(out + (size_t)row * Cc))[tid] = o4;
}

// ---------------------------------------------------------------------------
// tf32 tensor-core GEMM: C[M,N] = A[M,K] @ B[K,N]  (+bias/residual/gelu)
// BM=BN=128, BK=32, 256 threads = 8 warps (2x4 warp grid, 64x32 warp tiles).
// cp.async double-buffered smem. A smem stride 36, B smem stride 136
// (both conflict-free for fragment LDS).
// EPI: 0 = plain, 1 = +bias+residual, 2 = +bias then exact GELU
// ---------------------------------------------------------------------------
constexpr int AS_STRIDE = 36;
constexpr int BS_STRIDE = 136;
constexpr int ASZ = 128 * AS_STRIDE;            // floats per A stage (4608)
constexpr int BSZ = 32 * BS_STRIDE;             // floats per B stage (4352)
constexpr int GEMM_SMEM = 2 * (ASZ + BSZ) * 4;  // 71680 bytes

template <int EPI>
__global__ __launch_bounds__(256, 2) void tgemm(
    const float* __restrict__ A, const float* __restrict__ Bm,
    const float* __restrict__ bias, const float* __restrict__ res,
    float* __restrict__ Cout, int Mn, int Nn, int Kn) {
    extern __shared__ float smem_g[];
    float* AsB = smem_g;
    float* BsB = smem_g + 2 * ASZ;

    int tid = threadIdx.x, lane = tid & 31, w = tid >> 5;
    int wm = w >> 2, wn = w & 3;           // 2 x 4 warp grid
    int row0 = blockIdx.y * 128, col0 = blockIdx.x * 128;
    int r = lane >> 2, c = lane & 3;

    float acc[4][4][4];
    #pragma unroll
    for (int i = 0; i < 4; i++)
        #pragma unroll
        for (int j = 0; j < 4; j++)
            #pragma unroll
            for (int k = 0; k < 4; k++) acc[i][j][k] = 0.f;

    uint32_t asBase = (uint32_t)__cvta_generic_to_shared(AsB);
    uint32_t bsBase = (uint32_t)__cvta_generic_to_shared(BsB);

    auto loadA = [&](int st, int k0) {
        #pragma unroll
        for (int i = 0; i < 4; i++) {
            int p = tid + i * 256;
            int rr = p >> 3, c4 = p & 7;
            uint32_t sa = asBase + (uint32_t)(st * ASZ + rr * AS_STRIDE + c4 * 4) * 4u;
            cp16(sa, A + (size_t)(row0 + rr) * Kn + k0 + c4 * 4);
        }
    };
    auto loadB = [&](int st, int k0) {
        #pragma unroll
        for (int i = 0; i < 4; i++) {
            int p = tid + i * 256;
            int rr = p >> 5, c4 = p & 31;
            uint32_t sa = bsBase + (uint32_t)(st * BSZ + rr * BS_STRIDE + c4 * 4) * 4u;
            cp16(sa, Bm + (size_t)(k0 + rr) * Nn + col0 + c4 * 4);
        }
    };

    loadA(0, 0); loadB(0, 0);
    asm volatile("cp.async.commit_group;\n" ::: "memory");

    int nk = Kn >> 5;
    for (int kt = 0; kt < nk; kt++) {
        int st = kt & 1;
        if (kt + 1 < nk) { loadA(st ^ 1, (kt + 1) * 32); loadB(st ^ 1, (kt + 1) * 32); }
        asm volatile("cp.async.commit_group;\n" ::: "memory");
        asm volatile("cp.async.wait_group 1;\n" ::: "memory");
        __syncthreads();

        const float* Asp = AsB + st * ASZ;
        const float* Bsp = BsB + st * BSZ;
        #pragma unroll
        for (int kk = 0; kk < 4; kk++) {
            int k = kk * 8;
            uint32_t af[4][4], bf[4][2];
            #pragma unroll
            for (int mi = 0; mi < 4; mi++) {
                int m0 = wm * 64 + mi * 16;
                af[mi][0] = __float_as_uint(Asp[(m0 + r) * AS_STRIDE + k + c]);
                af[mi][1] = __float_as_uint(Asp[(m0 + r + 8) * AS_STRIDE + k + c]);
                af[mi][2] = __float_as_uint(Asp[(m0 + r) * AS_STRIDE + k + c + 4]);
                af[mi][3] = __float_as_uint(Asp[(m0 + r + 8) * AS_STRIDE + k + c + 4]);
            }
            #pragma unroll
            for (int ni = 0; ni < 4; ni++) {
                int n0 = wn * 32 + ni * 8;
                bf[ni][0] = __float_as_uint(Bsp[(k + c) * BS_STRIDE + n0 + r]);
                bf[ni][1] = __float_as_uint(Bsp[(k + c + 4) * BS_STRIDE + n0 + r]);
            }
            #pragma unroll
            for (int mi = 0; mi < 4; mi++)
                #pragma unroll
                for (int ni = 0; ni < 4; ni++)
                    mma_tf32(acc[mi][ni], af[mi], bf[ni]);
        }
        __syncthreads();
    }

    // Epilogue: C fragment rows r/r+8, cols 2c/2c+1
    #pragma unroll
    for (int mi = 0; mi < 4; mi++) {
        int rr0 = row0 + wm * 64 + mi * 16 + r;
        #pragma unroll
        for (int ni = 0; ni < 4; ni++) {
            int cc = col0 + wn * 32 + ni * 8 + 2 * c;
            float v0 = acc[mi][ni][0], v1 = acc[mi][ni][1];
            float v2 = acc[mi][ni][2], v3 = acc[mi][ni][3];
            if (EPI == 1) {
                float b0 = bias[cc], b1 = bias[cc + 1];
                float2 r0 = *(const float2*)&res[(size_t)rr0 * Nn + cc];
                float2 r1 = *(const float2*)&res[(size_t)(rr0 + 8) * Nn + cc];
                v0 += b0 + r0.x; v1 += b1 + r0.y;
                v2 += b0 + r1.x; v3 += b1 + r1.y;
            } else if (EPI == 2) {
                float b0 = bias[cc], b1 = bias[cc + 1];
                v0 += b0; v1 += b1; v2 += b0; v3 += b1;
                v0 = 0.5f * v0 * (1.0f + erff(v0 * 0.70710678118654752f));
                v1 = 0.5f * v1 * (1.0f + erff(v1 * 0.70710678118654752f));
                v2 = 0.5f * v2 * (1.0f + erff(v2 * 0.70710678118654752f));
                v3 = 0.5f * v3 * (1.0f + erff(v3 * 0.70710678118654752f));
            }
            *(float2*)&Cout[(size_t)rr0 * Nn + cc]       = make_float2(v0, v1);
            *(float2*)&Cout[(size_t)(rr0 + 8) * Nn + cc] = make_float2(v2, v3);
        }
    }
}

// ---------------------------------------------------------------------------
// Tensor-core flash attention with permutation mask.
// Block: 128 queries (8 warps x 16 rows), KV tiles of 64, D=64.
// Q held in registers as tf32 A-fragments for the whole kernel.
// S accumulated in mma C-fragments; mask+online softmax on fragments;
// P round-trips through per-warp smem to become the A operand of P@V.
// ---------------------------------------------------------------------------
constexpr int KSS = 68;             // Ks stride (bank: 4r+c distinct)
constexpr int VSS = 72;             // Vs stride (bank: 8c+r distinct)
constexpr int PSS = 68;             // Ps stride
constexpr int KS_F = 64 * KSS;      // 4352 floats
constexpr int VS_F = 64 * VSS;      // 4608
constexpr int PS_F = 128 * PSS;     // 8704
constexpr int ATTN_SMEM = (KS_F + VS_F + PS_F) * 4 + 64 * 4;  // 70912 B

__global__ __launch_bounds__(256, 2) void attn_mma(
    const float* __restrict__ qkv, const int* __restrict__ perm,
    float* __restrict__ out) {
    extern __shared__ float smem_a[];
    float* Ks = smem_a;
    float* Vs = Ks + KS_F;
    float* Ps = Vs + VS_F;
    int*   permS = (int*)(Ps + PS_F);

    int tid = threadIdx.x, lane = tid & 31, w = tid >> 5;
    int r = lane >> 2, c = lane & 3;
    int q0 = blockIdx.x * 128;
    int h = blockIdx.y, b = blockIdx.z;

    // Load Q fragments directly from gmem (once), keep as tf32 bits.
    const float* qb = qkv + ((size_t)(b * Tt + q0 + w * 16)) * 3072 + h * 64;
    uint32_t qa[8][4];
    #pragma unroll
    for (int j = 0; j < 8; j++) {
        qa[j][0] = __float_as_uint(qb[(size_t)r * 3072 + j * 8 + c]);
        qa[j][1] = __float_as_uint(qb[(size_t)(r + 8) * 3072 + j * 8 + c]);
        qa[j][2] = __float_as_uint(qb[(size_t)r * 3072 + j * 8 + c + 4]);
        qa[j][3] = __float_as_uint(qb[(size_t)(r + 8) * 3072 + j * 8 + c + 4]);
    }

    float oacc[8][4];
    #pragma unroll
    for (int i = 0; i < 8; i++)
        #pragma unroll
        for (int k = 0; k < 4; k++) oacc[i][k] = 0.f;
    float m0 = -1e30f, m1 = -1e30f, l0 = 0.f, l1 = 0.f;
    int q_lo = q0 + w * 16 + r, q_hi = q_lo + 8;
    float* Pw = Ps + (w * 16) * PSS;   // per-warp private P region

    for (int k0 = 0; k0 < Tt; k0 += 64) {
        __syncthreads();   // previous tile's PV done reading Ks/Vs
        // Load K and V tiles (coalesced float4)
        #pragma unroll
        for (int i = 0; i < 4; i++) {
            int p = tid + i * 256;
            int kr = p >> 4, c4 = p & 15;
            const float* gk = qkv + ((size_t)(b * Tt + k0 + kr)) * 3072 + 1024 + h * 64 + c4 * 4;
            float4 kx = *(const float4*)gk;
            *(float4*)&Ks[kr * KSS + c4 * 4] = kx;
            float4 vx = *(const float4*)(gk + 1024);
            *(float4*)&Vs[kr * VSS + c4 * 4] = vx;
        }
        if (tid < 64) permS[tid] = perm[k0 + tid];
        __syncthreads();

        // S = Q @ K^T  (8 d-chunks x 8 key-tiles of mma)
        float sacc[8][4];
        #pragma unroll
        for (int i = 0; i < 8; i++)
            #pragma unroll
            for (int k = 0; k < 4; k++) sacc[i][k] = 0.f;
        #pragma unroll
        for (int j = 0; j < 8; j++) {
            #pragma unroll
            for (int ni = 0; ni < 8; ni++) {
                uint32_t kb[2];
                kb[0] = __float_as_uint(Ks[(ni * 8 + r) * KSS + j * 8 + c]);
                kb[1] = __float_as_uint(Ks[(ni * 8 + r) * KSS + j * 8 + c + 4]);
                mma_tf32(sacc[ni], qa[j], kb);
            }
        }

        // Mask + scale + per-row max (rows r and r+8 within warp tile)
        float mx0 = -1e30f, mx1 = -1e30f;
        #pragma unroll
        for (int ni = 0; ni < 8; ni++) {
            int col = ni * 8 + 2 * c;
            int p0 = permS[col], p1 = permS[col + 1];
            sacc[ni][0] = (p0 > q_lo) ? -1e30f : sacc[ni][0] * 0.125f;
            sacc[ni][1] = (p1 > q_lo) ? -1e30f : sacc[ni][1] * 0.125f;
            sacc[ni][2] = (p0 > q_hi) ? -1e30f : sacc[ni][2] * 0.125f;
            sacc[ni][3] = (p1 > q_hi) ? -1e30f : sacc[ni][3] * 0.125f;
            mx0 = fmaxf(mx0, fmaxf(sacc[ni][0], sacc[ni][1]));
            mx1 = fmaxf(mx1, fmaxf(sacc[ni][2], sacc[ni][3]));
        }
        mx0 = fmaxf(mx0, __shfl_xor_sync(0xffffffffu, mx0, 1));
        mx0 = fmaxf(mx0, __shfl_xor_sync(0xffffffffu, mx0, 2));
        mx1 = fmaxf(mx1, __shfl_xor_sync(0xffffffffu, mx1, 1));
        mx1 = fmaxf(mx1, __shfl_xor_sync(0xffffffffu, mx1, 2));

        float nm0 = fmaxf(m0, mx0), nm1 = fmaxf(m1, mx1);
        float al0 = __expf(m0 - nm0), al1 = __expf(m1 - nm1);
        float ls0 = 0.f, ls1 = 0.f;
        #pragma unroll
        for (int ni = 0; ni < 8; ni++) {
            sacc[ni][0] = __expf(sacc[ni][0] - nm0);
            sacc[ni][1] = __expf(sacc[ni][1] - nm0);
            sacc[ni][2] = __expf(sacc[ni][2] - nm1);
            sacc[ni][3] = __expf(sacc[ni][3] - nm1);
            ls0 += sacc[ni][0] + sacc[ni][1];
            ls1 += sacc[ni][2] + sacc[ni][3];
        }
        ls0 += __shfl_xor_sync(0xffffffffu, ls0, 1);
        ls0 += __shfl_xor_sync(0xffffffffu, ls0, 2);
        ls1 += __shfl_xor_sync(0xffffffffu, ls1, 1);
        ls1 += __shfl_xor_sync(0xffffffffu, ls1, 2);
        l0 = l0 * al0 + ls0;
        l1 = l1 * al1 + ls1;
        m0 = nm0; m1 = nm1;
        #pragma unroll
        for (int ni = 0; ni < 8; ni++) {
            oacc[ni][0] *= al0; oacc[ni][1] *= al0;
            oacc[ni][2] *= al1; oacc[ni][3] *= al1;
        }

        // Write P to per-warp smem (C-frag layout), re-read as A-frags
        #pragma unroll
        for (int ni = 0; ni < 8; ni++) {
            int col = ni * 8 + 2 * c;
            *(float2*)&Pw[r * PSS + col]       = make_float2(sacc[ni][0], sacc[ni][1]);
            *(float2*)&Pw[(r + 8) * PSS + col] = make_float2(sacc[ni][2], sacc[ni][3]);
        }
        __syncwarp();

        // O += P @ V  (8 key-chunks x 8 d-tiles)
        #pragma unroll
        for (int j = 0; j < 8; j++) {
            uint32_t pa[4];
            pa[0] = __float_as_uint(Pw[r * PSS + j * 8 + c]);
            pa[1] = __float_as_uint(Pw[(r + 8) * PSS + j * 8 + c]);
            pa[2] = __float_as_uint(Pw[r * PSS + j * 8 + c + 4]);
            pa[3] = __float_as_uint(Pw[(r + 8) * PSS + j * 8 + c + 4]);
            #pragma unroll
            for (int ni = 0; ni < 8; ni++) {
                uint32_t vb[2];
                vb[0] = __float_as_uint(Vs[(j * 8 + c) * VSS + ni * 8 + r]);
                vb[1] = __float_as_uint(Vs[(j * 8 + c + 4) * VSS + ni * 8 + r]);
                mma_tf32(oacc[ni], pa, vb);
            }
        }
    }

    float inv0 = 1.0f / l0, inv1 = 1.0f / l1;
    float* ob = out + ((size_t)(b * Tt + q_lo)) * 1024 + h * 64;
    #pragma unroll
    for (int ni = 0; ni < 8; ni++) {
        int col = ni * 8 + 2 * c;
        *(float2*)&ob[col] = make_float2(oacc[ni][0] * inv0, oacc[ni][1] * inv0);
        *(float2*)&ob[(size_t)8 * 1024 + col] = make_float2(oacc[ni][2] * inv1, oacc[ni][3] * inv1);
    }
}

// ---------------------------------------------------------------------------
// Launch
// ---------------------------------------------------------------------------
extern "C" void kernel_launch(void* const* d_in, const int* in_sizes, int n_in,
                              void* d_out, int out_size) {
    (void)in_sizes; (void)n_in; (void)out_size;
    const float* x     = (const float*)d_in[0];
    const int*   perm  = (const int*)d_in[1];
    const float* Wqkv  = (const float*)d_in[2];
    const float* Wproj = (const float*)d_in[3];
    const float* bproj = (const float*)d_in[4];
    const float* ln1_g = (const float*)d_in[5];
    const float* ln1_b = (const float*)d_in[6];
    const float* ln2_g = (const float*)d_in[7];
    const float* ln2_b = (const float*)d_in[8];
    const float* Wff1  = (const float*)d_in[9];
    const float* bff1  = (const float*)d_in[10];
    const float* Wff2  = (const float*)d_in[11];
    const float* bff2  = (const float*)d_in[12];
    float* out = (float*)d_out;

    void *ph, *pqkv, *patt, *px2, *pff;
    cudaGetSymbolAddress(&ph,   g_h);
    cudaGetSymbolAddress(&pqkv, g_qkv);
    cudaGetSymbolAddress(&patt, g_att);
    cudaGetSymbolAddress(&px2,  g_x2);
    cudaGetSymbolAddress(&pff,  g_ff);
    float* h   = (float*)ph;
    float* qkv = (float*)pqkv;
    float* att = (float*)patt;
    float* x2  = (float*)px2;
    float* ff  = (float*)pff;

    cudaFuncSetAttribute((const void*)tgemm<0>,
                         cudaFuncAttributeMaxDynamicSharedMemorySize, GEMM_SMEM);
    cudaFuncSetAttribute((const void*)tgemm<1>,
                         cudaFuncAttributeMaxDynamicSharedMemorySize, GEMM_SMEM);
    cudaFuncSetAttribute((const void*)tgemm<2>,
                         cudaFuncAttributeMaxDynamicSharedMemorySize, GEMM_SMEM);
    cudaFuncSetAttribute((const void*)attn_mma,
                         cudaFuncAttributeMaxDynamicSharedMemorySize, ATTN_SMEM);

    // 1. h = LN1(x)
    ln_kernel<<<Mm, 256>>>(x, ln1_g, ln1_b, h);
    // 2. qkv = h @ Wqkv
    tgemm<0><<<dim3(3 * Cc / 128, Mm / 128), 256, GEMM_SMEM>>>(
        h, Wqkv, nullptr, nullptr, qkv, Mm, 3 * Cc, Cc);
    // 3. attention -> att
    attn_mma<<<dim3(Tt / 128, Hh, Bb), 256, ATTN_SMEM>>>(qkv, perm, att);
    // 4. x2 = x + att @ Wproj + bproj
    tgemm<1><<<dim3(Cc / 128, Mm / 128), 256, GEMM_SMEM>>>(
        att, Wproj, bproj, x, x2, Mm, Cc, Cc);
    // 5. h = LN2(x2)
    ln_kernel<<<Mm, 256>>>(x2, ln2_g, ln2_b, h);
    // 6. ff = gelu(h @ Wff1 + bff1)
    tgemm<2><<<dim3(FFf / 128, Mm / 128), 256, GEMM_SMEM>>>(
        h, Wff1, bff1, nullptr, ff, Mm, FFf, Cc);
    // 7. out = x2 + ff @ Wff2 + bff2
    tgemm<1><<<dim3(Cc / 128, Mm / 128), 256, GEMM_SMEM>>>(
        ff, Wff2, bff2, x2, out, Mm, Cc, FFf);
}